// round 1
// baseline (speedup 1.0000x reference)
#include <cuda_runtime.h>
#include <math.h>

// Problem constants
#define BB 2
#define NN 2048
#define EE 1024
#define HH 16
#define DD 64
#define MTOT (BB * NN)   // 4096 rows for the projection GEMMs

// ---------------------------------------------------------------------------
// Scratch (device globals -> no allocations, graph-capture safe)
// ---------------------------------------------------------------------------
__device__ float g_q [BB * HH * NN * DD];   // [B,H,N,D]
__device__ float g_k [BB * HH * NN * DD];
__device__ float g_v [BB * HH * NN * DD];
__device__ float g_ao[(size_t)MTOT * EE];   // attention output, [B,N,E] row-major

// ---------------------------------------------------------------------------
// GEMM: Y[m,e] = sum_k X[m,k] * W[e,k] + bias[e]
//   X: [MTOT, EE] row-major, W: [EE, EE] row-major (we multiply by W^T)
//   SCATTER=1 -> write head-split [B,H,N,D]; SCATTER=0 -> plain [MTOT,EE]
// 128x128 tile, BK=8, 256 threads, 8x8 register microtile.
// ---------------------------------------------------------------------------
template<int SCATTER>
__global__ __launch_bounds__(256)
void gemm_bias_kernel(const float* __restrict__ X,
                      const float* __restrict__ W,
                      const float* __restrict__ bias,
                      float* __restrict__ Y)
{
    constexpr int BM = 128, BN = 128, BK = 8;
    __shared__ float As[BK][BM];
    __shared__ float Bs[BK][BN];

    const int tid = threadIdx.x;
    const int m0 = blockIdx.y * BM;
    const int n0 = blockIdx.x * BN;
    const int tr = tid >> 4;      // 0..15, owns rows tr*8..tr*8+7
    const int tc = tid & 15;      // 0..15, owns cols tc*8..tc*8+7

    // Loader mapping: each thread loads one float4 per tile per operand
    const int lr = tid >> 1;      // 0..127
    const int lc = tid & 1;       // 0..1
    const float* Xp = X + (size_t)(m0 + lr) * EE + lc * 4;
    const float* Wp = W + (size_t)(n0 + lr) * EE + lc * 4;

    float acc[8][8];
    #pragma unroll
    for (int i = 0; i < 8; ++i)
        #pragma unroll
        for (int j = 0; j < 8; ++j) acc[i][j] = 0.f;

    for (int kt = 0; kt < EE; kt += BK) {
        float4 av = *(const float4*)(Xp + kt);
        float4 bv = *(const float4*)(Wp + kt);
        As[lc * 4 + 0][lr] = av.x;
        As[lc * 4 + 1][lr] = av.y;
        As[lc * 4 + 2][lr] = av.z;
        As[lc * 4 + 3][lr] = av.w;
        Bs[lc * 4 + 0][lr] = bv.x;
        Bs[lc * 4 + 1][lr] = bv.y;
        Bs[lc * 4 + 2][lr] = bv.z;
        Bs[lc * 4 + 3][lr] = bv.w;
        __syncthreads();

        #pragma unroll
        for (int k = 0; k < BK; ++k) {
            float a_[8], b_[8];
            #pragma unroll
            for (int i = 0; i < 8; ++i) a_[i] = As[k][tr * 8 + i];
            #pragma unroll
            for (int j = 0; j < 8; ++j) b_[j] = Bs[k][tc * 8 + j];
            #pragma unroll
            for (int i = 0; i < 8; ++i)
                #pragma unroll
                for (int j = 0; j < 8; ++j)
                    acc[i][j] = fmaf(a_[i], b_[j], acc[i][j]);
        }
        __syncthreads();
    }

    #pragma unroll
    for (int i = 0; i < 8; ++i) {
        const int m = m0 + tr * 8 + i;
        #pragma unroll
        for (int j = 0; j < 8; ++j) {
            const int e = n0 + tc * 8 + j;
            const float v = acc[i][j] + bias[e];
            if (SCATTER) {
                const int b = m >> 11;          // m / NN
                const int n = m & (NN - 1);
                const int h = e >> 6;           // e / DD
                const int d = e & (DD - 1);
                Y[((((size_t)b * HH + h) * NN) + n) * DD + d] = v;
            } else {
                Y[(size_t)m * EE + e] = v;
            }
        }
    }
}

// ---------------------------------------------------------------------------
// Flash attention (fp32), full (non-causal) attention over N=2048 keys.
// Reference quirk: softmax FIRST, then divide by sqrt(E)=32 (no pre-scale).
// BQ=64 queries/block, BKV=64 keys/iter, 256 threads (16x16, 4x4 microtiles).
// Output merged heads: [B, N, E].
// ---------------------------------------------------------------------------
#define FA_STRIDE 65   // smem row stride padding (2-way worst-case conflicts)

__global__ __launch_bounds__(256)
void flash_attn_kernel(const float* __restrict__ qb,
                       const float* __restrict__ kb,
                       const float* __restrict__ vb,
                       float* __restrict__ out)
{
    extern __shared__ float sm[];
    float* Qs   = sm;                         // 64 * 65
    float* Ks   = Qs + 64 * FA_STRIDE;
    float* Vs   = Ks + 64 * FA_STRIDE;
    float* Ss   = Vs + 64 * FA_STRIDE;
    float* mrow = Ss + 64 * FA_STRIDE;        // 64
    float* lrow = mrow + 64;                  // 64
    float* arow = lrow + 64;                  // 64

    const int tid = threadIdx.x;
    const int q0  = blockIdx.x * 64;
    const int bh  = blockIdx.y;               // b*HH + h
    const int b   = bh >> 4;
    const int h   = bh & (HH - 1);

    const int tr = tid >> 4;   // 0..15 -> rows tr*4..+3
    const int tc = tid & 15;   // 0..15 -> cols tc*4..+3

    // Load Q tile (coalesced float4 gmem reads, scalar smem stores)
    const float* qg = qb + ((size_t)bh * NN + q0) * DD;
    #pragma unroll
    for (int it = 0; it < 4; ++it) {
        const int lin = it * 1024 + tid * 4;
        const int r = lin >> 6, c = lin & 63;
        float4 v = *(const float4*)(qg + lin);
        float* dst = Qs + r * FA_STRIDE + c;
        dst[0] = v.x; dst[1] = v.y; dst[2] = v.z; dst[3] = v.w;
    }
    if (tid < 64) { mrow[tid] = -1e30f; lrow[tid] = 0.f; }

    float o_acc[4][4];
    #pragma unroll
    for (int i = 0; i < 4; ++i)
        #pragma unroll
        for (int j = 0; j < 4; ++j) o_acc[i][j] = 0.f;

    const float* kg = kb + (size_t)bh * NN * DD;
    const float* vg = vb + (size_t)bh * NN * DD;

    for (int kv0 = 0; kv0 < NN; kv0 += 64) {
        __syncthreads();   // protect Ks/Vs/Ss from previous iteration's readers
        // Load K and V tiles
        #pragma unroll
        for (int it = 0; it < 4; ++it) {
            const int lin = it * 1024 + tid * 4;
            const int r = lin >> 6, c = lin & 63;
            float4 kv4 = *(const float4*)(kg + (size_t)kv0 * DD + lin);
            float4 vv4 = *(const float4*)(vg + (size_t)kv0 * DD + lin);
            float* kd = Ks + r * FA_STRIDE + c;
            float* vd = Vs + r * FA_STRIDE + c;
            kd[0] = kv4.x; kd[1] = kv4.y; kd[2] = kv4.z; kd[3] = kv4.w;
            vd[0] = vv4.x; vd[1] = vv4.y; vd[2] = vv4.z; vd[3] = vv4.w;
        }
        __syncthreads();

        // GEMM1: S = Q @ K^T  (64x64x64)
        float s_acc[4][4];
        #pragma unroll
        for (int i = 0; i < 4; ++i)
            #pragma unroll
            for (int j = 0; j < 4; ++j) s_acc[i][j] = 0.f;

        #pragma unroll 8
        for (int d = 0; d < 64; ++d) {
            float a_[4], b_[4];
            #pragma unroll
            for (int i = 0; i < 4; ++i) a_[i] = Qs[(tr * 4 + i) * FA_STRIDE + d];
            #pragma unroll
            for (int j = 0; j < 4; ++j) b_[j] = Ks[(tc * 4 + j) * FA_STRIDE + d];
            #pragma unroll
            for (int i = 0; i < 4; ++i)
                #pragma unroll
                for (int j = 0; j < 4; ++j)
                    s_acc[i][j] = fmaf(a_[i], b_[j], s_acc[i][j]);
        }
        #pragma unroll
        for (int i = 0; i < 4; ++i)
            #pragma unroll
            for (int j = 0; j < 4; ++j)
                Ss[(tr * 4 + i) * FA_STRIDE + tc * 4 + j] = s_acc[i][j];
        __syncthreads();

        // Online softmax update: 4 threads per row (row = tid/4)
        {
            const int r  = tid >> 2;
            const int l4 = tid & 3;
            float* srow = Ss + r * FA_STRIDE + l4 * 16;
            float tmax = -1e30f;
            #pragma unroll
            for (int jj = 0; jj < 16; ++jj) tmax = fmaxf(tmax, srow[jj]);
            tmax = fmaxf(tmax, __shfl_xor_sync(0xffffffffu, tmax, 1));
            tmax = fmaxf(tmax, __shfl_xor_sync(0xffffffffu, tmax, 2));
            const float mold = mrow[r];
            const float mnew = fmaxf(mold, tmax);
            float psum = 0.f;
            #pragma unroll
            for (int jj = 0; jj < 16; ++jj) {
                const float p = __expf(srow[jj] - mnew);
                srow[jj] = p;
                psum += p;
            }
            psum += __shfl_xor_sync(0xffffffffu, psum, 1);
            psum += __shfl_xor_sync(0xffffffffu, psum, 2);
            if (l4 == 0) {
                const float a = __expf(mold - mnew);  // 0 on first tile
                arow[r] = a;
                lrow[r] = lrow[r] * a + psum;
                mrow[r] = mnew;
            }
        }
        __syncthreads();

        // GEMM2: O = O*alpha + P @ V  (64x64x64)
        #pragma unroll
        for (int i = 0; i < 4; ++i) {
            const float a = arow[tr * 4 + i];
            #pragma unroll
            for (int j = 0; j < 4; ++j) o_acc[i][j] *= a;
        }
        #pragma unroll 8
        for (int jk = 0; jk < 64; ++jk) {
            float p_[4], v_[4];
            #pragma unroll
            for (int i = 0; i < 4; ++i) p_[i] = Ss[(tr * 4 + i) * FA_STRIDE + jk];
            #pragma unroll
            for (int j = 0; j < 4; ++j) v_[j] = Vs[jk * FA_STRIDE + tc * 4 + j];
            #pragma unroll
            for (int i = 0; i < 4; ++i)
                #pragma unroll
                for (int j = 0; j < 4; ++j)
                    o_acc[i][j] = fmaf(p_[i], v_[j], o_acc[i][j]);
        }
    }
    __syncthreads();

    // Epilogue: divide by l (softmax denom) and by sqrt(E)=32 (reference quirk)
    #pragma unroll
    for (int i = 0; i < 4; ++i) {
        const int row = tr * 4 + i;
        const float inv = 1.0f / (lrow[row] * 32.0f);
        #pragma unroll
        for (int j = 0; j < 4; ++j) {
            const int col = tc * 4 + j;
            out[((size_t)b * NN + (q0 + row)) * EE + h * DD + col] =
                o_acc[i][j] * inv;
        }
    }
}

// ---------------------------------------------------------------------------
// Launcher
// ---------------------------------------------------------------------------
extern "C" void kernel_launch(void* const* d_in, const int* in_sizes, int n_in,
                              void* d_out, int out_size)
{
    const float* queries = (const float*)d_in[0];
    const float* keys    = (const float*)d_in[1];
    const float* values  = (const float*)d_in[2];
    const float* Wq = (const float*)d_in[3];
    const float* bq = (const float*)d_in[4];
    const float* Wk = (const float*)d_in[5];
    const float* bk = (const float*)d_in[6];
    const float* Wv = (const float*)d_in[7];
    const float* bv = (const float*)d_in[8];
    const float* Wp = (const float*)d_in[9];
    const float* bp = (const float*)d_in[10];
    float* out = (float*)d_out;

    float *pq, *pk, *pv, *pao;
    cudaGetSymbolAddress((void**)&pq,  g_q);
    cudaGetSymbolAddress((void**)&pk,  g_k);
    cudaGetSymbolAddress((void**)&pv,  g_v);
    cudaGetSymbolAddress((void**)&pao, g_ao);

    const dim3 gemm_grid(EE / 128, MTOT / 128);   // (8, 32)
    gemm_bias_kernel<1><<<gemm_grid, 256>>>(queries, Wq, bq, pq);
    gemm_bias_kernel<1><<<gemm_grid, 256>>>(keys,    Wk, bk, pk);
    gemm_bias_kernel<1><<<gemm_grid, 256>>>(values,  Wv, bv, pv);

    const int fa_smem = (4 * 64 * FA_STRIDE + 3 * 64) * (int)sizeof(float); // 67328
    cudaFuncSetAttribute(flash_attn_kernel,
                         cudaFuncAttributeMaxDynamicSharedMemorySize, fa_smem);
    const dim3 fa_grid(NN / 64, BB * HH);         // (32, 32)
    flash_attn_kernel<<<fa_grid, 256, fa_smem>>>(pq, pk, pv, pao);

    gemm_bias_kernel<0><<<gemm_grid, 256>>>(pao, Wp, bp, out);
}

// round 4
// speedup vs baseline: 1.4204x; 1.4204x over previous
#include <cuda_runtime.h>
#include <stdint.h>

#define BB 2
#define NN 2048
#define EE 1024
#define HH 16
#define DD 64
#define MTOT (BB * NN)

// swizzle for B-operand tiles (row width 64/128 floats): xors bits 2-4 of n with k
#define BXOR(k) (((((k) & 3) << 3)) | ((((k) & 4) << 2)))

// ---------------------------------------------------------------------------
// Scratch
// ---------------------------------------------------------------------------
__device__ float g_q [BB * HH * NN * DD];
__device__ float g_k [BB * HH * NN * DD];
__device__ float g_v [BB * HH * NN * DD];
__device__ float g_ao[(size_t)MTOT * EE];

// ---------------------------------------------------------------------------
// Helpers
// ---------------------------------------------------------------------------
__device__ __forceinline__ uint32_t f2tf(float x) {
    uint32_t u;
    asm("cvt.rna.tf32.f32 %0, %1;" : "=r"(u) : "f"(x));
    return u;
}

// 3xTF32 split: x ~= hi + lo, both representable in tf32
__device__ __forceinline__ void tfsplit(float x, uint32_t& hi, uint32_t& lo) {
    hi = f2tf(x);
    lo = f2tf(x - __uint_as_float(hi));
}

__device__ __forceinline__ void mma8(float& c0, float& c1, float& c2, float& c3,
                                     uint32_t a0, uint32_t a1, uint32_t a2, uint32_t a3,
                                     uint32_t b0, uint32_t b1) {
    asm volatile(
        "mma.sync.aligned.m16n8k8.row.col.f32.tf32.tf32.f32 "
        "{%0,%1,%2,%3}, {%4,%5,%6,%7}, {%8,%9}, {%0,%1,%2,%3};\n"
        : "+f"(c0), "+f"(c1), "+f"(c2), "+f"(c3)
        : "r"(a0), "r"(a1), "r"(a2), "r"(a3), "r"(b0), "r"(b1));
}

// C += A*B with 3xtf32 compensation: Alo*Bhi + Ahi*Blo + Ahi*Bhi
__device__ __forceinline__ void mma8_3x(float* c,
                                        const uint32_t* ah, const uint32_t* al,
                                        const uint32_t* bh, const uint32_t* bl) {
    mma8(c[0], c[1], c[2], c[3], al[0], al[1], al[2], al[3], bh[0], bh[1]);
    mma8(c[0], c[1], c[2], c[3], ah[0], ah[1], ah[2], ah[3], bl[0], bl[1]);
    mma8(c[0], c[1], c[2], c[3], ah[0], ah[1], ah[2], ah[3], bh[0], bh[1]);
}

// ---------------------------------------------------------------------------
// 3xtf32 GEMM: Y[m,e] = X[m,:] . W[e,:] + bias[e]
// BM=128 BN=128 BK=32, 8 warps (2x4), warp tile 64x32, mma m16n8k8.
// smem holds raw fp32; hi/lo split recomputed at fragment load.
// ---------------------------------------------------------------------------
template<int SCATTER>
__global__ __launch_bounds__(256)
void gemm_tf32(const float* __restrict__ X,
               const float* __restrict__ W,
               const float* __restrict__ bias,
               float* __restrict__ Y)
{
    __shared__ float As[128 * 32];  // [m][k^((m&7)<<2)]
    __shared__ float Bs[32 * 128];  // [k][n^BXOR(k)]

    const int tid  = threadIdx.x;
    const int lane = tid & 31;
    const int warp = tid >> 5;
    const int wm = warp >> 2, wn = warp & 3;
    const int g = lane >> 2, t4 = lane & 3;
    const int m0 = blockIdx.y * 128, n0 = blockIdx.x * 128;

    const int aRow = tid >> 3, aK4 = tid & 7;   // A loader
    const int bN = tid >> 1, bKh = tid & 1;     // B loader

    float acc[4][4][4];
    #pragma unroll
    for (int i = 0; i < 4; ++i)
        #pragma unroll
        for (int j = 0; j < 4; ++j)
            #pragma unroll
            for (int c = 0; c < 4; ++c) acc[i][j][c] = 0.f;

    const float* Xb = X + (size_t)m0 * EE;
    const float* Wb = W + (size_t)n0 * EE;

    for (int kt = 0; kt < EE; kt += 32) {
        __syncthreads();
        #pragma unroll
        for (int i = 0; i < 4; ++i) {
            const int m = aRow + 32 * i;
            float4 v = *(const float4*)(Xb + (size_t)m * EE + kt + aK4 * 4);
            *(float4*)(&As[m * 32 + ((aK4 * 4) ^ ((m & 7) << 2))]) = v;
        }
        #pragma unroll
        for (int j = 0; j < 4; ++j) {
            const int kb = (2 * j + bKh) * 4;
            float4 v = *(const float4*)(Wb + (size_t)bN * EE + kt + kb);
            Bs[(kb + 0) * 128 + (bN ^ BXOR(kb + 0))] = v.x;
            Bs[(kb + 1) * 128 + (bN ^ BXOR(kb + 1))] = v.y;
            Bs[(kb + 2) * 128 + (bN ^ BXOR(kb + 2))] = v.z;
            Bs[(kb + 3) * 128 + (bN ^ BXOR(kb + 3))] = v.w;
        }
        __syncthreads();

        #pragma unroll
        for (int kk = 0; kk < 4; ++kk) {
            const int c0 = kk * 8 + t4;
            uint32_t ah[4][4], al[4][4];
            #pragma unroll
            for (int mt = 0; mt < 4; ++mt) {
                const int r0 = wm * 64 + mt * 16 + g;
                const int x = (r0 & 7) << 2;
                tfsplit(As[r0 * 32 + (c0 ^ x)],            ah[mt][0], al[mt][0]);
                tfsplit(As[(r0 + 8) * 32 + (c0 ^ x)],      ah[mt][1], al[mt][1]);
                tfsplit(As[r0 * 32 + ((c0 + 4) ^ x)],      ah[mt][2], al[mt][2]);
                tfsplit(As[(r0 + 8) * 32 + ((c0 + 4) ^ x)],ah[mt][3], al[mt][3]);
            }
            uint32_t bh[4][2], bl[4][2];
            #pragma unroll
            for (int nt = 0; nt < 4; ++nt) {
                const int nb = wn * 32 + nt * 8 + g;
                tfsplit(Bs[c0 * 128 + (nb ^ BXOR(c0))],           bh[nt][0], bl[nt][0]);
                tfsplit(Bs[(c0 + 4) * 128 + (nb ^ BXOR(c0 + 4))], bh[nt][1], bl[nt][1]);
            }
            #pragma unroll
            for (int mt = 0; mt < 4; ++mt)
                #pragma unroll
                for (int nt = 0; nt < 4; ++nt)
                    mma8_3x(acc[mt][nt], ah[mt], al[mt], bh[nt], bl[nt]);
        }
    }

    #pragma unroll
    for (int mt = 0; mt < 4; ++mt) {
        const int r0 = m0 + wm * 64 + mt * 16 + g;
        #pragma unroll
        for (int nt = 0; nt < 4; ++nt) {
            const int c = n0 + wn * 32 + nt * 8 + 2 * t4;
            const float bv0 = bias[c], bv1 = bias[c + 1];
            float2 v0 = make_float2(acc[mt][nt][0] + bv0, acc[mt][nt][1] + bv1);
            float2 v1 = make_float2(acc[mt][nt][2] + bv0, acc[mt][nt][3] + bv1);
            if (SCATTER) {
                const int h = c >> 6, d = c & 63;
                const int b0i = r0 >> 11, n0i = r0 & (NN - 1);
                *(float2*)(&Y[((((size_t)b0i * HH + h) * NN) + n0i) * DD + d]) = v0;
                const int r1 = r0 + 8;
                const int b1i = r1 >> 11, n1i = r1 & (NN - 1);
                *(float2*)(&Y[((((size_t)b1i * HH + h) * NN) + n1i) * DD + d]) = v1;
            } else {
                *(float2*)(&Y[(size_t)r0 * EE + c]) = v0;
                *(float2*)(&Y[(size_t)(r0 + 8) * EE + c]) = v1;
            }
        }
    }
}

// ---------------------------------------------------------------------------
// Flash attention, 3xtf32 mma. BQ=64, BKV=64, 8 warps (2x4).
// mma1: S^T[kv][q] = K . Q^T      (Q transposed once per block)
// softmax column-wise over kv (online m/l), quirk: /sqrt(E)=32 post-softmax
// mma2: O[q][d] += P . V          (P read transposed from S^T, conflict-free)
// ---------------------------------------------------------------------------
__global__ __launch_bounds__(256)
void flash_tf32(const float* __restrict__ qb,
                const float* __restrict__ kb,
                const float* __restrict__ vb,
                float* __restrict__ out)
{
    extern __shared__ char smraw[];
    float* Qt = (float*)smraw;             // [d][q ^ BXOR(d)]
    float* Ks = Qt + 64 * 64;              // [kv][d ^ ((kv&7)<<2)]
    float* Vs = Ks + 64 * 64;              // [kv][d ^ BXOR(kv)]
    float* St = Vs + 64 * 64;              // [kv][q ^ ((kv&3)<<3)]
    float* mrow = St + 64 * 64;
    float* lrow = mrow + 64;
    float* arow = lrow + 64;
    float* pmax = arow + 64;               // [4][64]
    float* psum = pmax + 256;              // [4][64]

    const int tid  = threadIdx.x;
    const int lane = tid & 31;
    const int warp = tid >> 5;
    const int wm = warp >> 2, wn = warp & 3;
    const int g = lane >> 2, t4 = lane & 3;

    const int q0 = blockIdx.x * 64;
    const int bh = blockIdx.y;
    const int b  = bh >> 4;
    const int h  = bh & (HH - 1);

    if (tid < 64) { mrow[tid] = -1e30f; lrow[tid] = 0.f; }

    // Q transpose (once per block)
    const float* Qg = qb + ((size_t)bh * NN + q0) * DD;
    const int d4 = tid & 15, row0 = tid >> 4;
    #pragma unroll
    for (int i = 0; i < 4; ++i) {
        const int q = row0 + 16 * i;
        float4 v = *(const float4*)(Qg + (size_t)q * DD + d4 * 4);
        const int dd = d4 * 4;
        Qt[(dd + 0) * 64 + (q ^ BXOR(dd + 0))] = v.x;
        Qt[(dd + 1) * 64 + (q ^ BXOR(dd + 1))] = v.y;
        Qt[(dd + 2) * 64 + (q ^ BXOR(dd + 2))] = v.z;
        Qt[(dd + 3) * 64 + (q ^ BXOR(dd + 3))] = v.w;
    }

    float oacc[2][2][4];
    #pragma unroll
    for (int i = 0; i < 2; ++i)
        #pragma unroll
        for (int j = 0; j < 2; ++j)
            #pragma unroll
            for (int c = 0; c < 4; ++c) oacc[i][j][c] = 0.f;

    const float* Kg = kb + (size_t)bh * NN * DD;
    const float* Vg = vb + (size_t)bh * NN * DD;

    for (int kv0 = 0; kv0 < NN; kv0 += 64) {
        __syncthreads();
        #pragma unroll
        for (int i = 0; i < 4; ++i) {
            const int kv = row0 + 16 * i;
            float4 kv4 = *(const float4*)(Kg + (size_t)(kv0 + kv) * DD + d4 * 4);
            float4 vv4 = *(const float4*)(Vg + (size_t)(kv0 + kv) * DD + d4 * 4);
            *(float4*)(&Ks[kv * 64 + ((d4 * 4) ^ ((kv & 7) << 2))]) = kv4;
            *(float4*)(&Vs[kv * 64 + ((d4 * 4) ^ BXOR(kv))]) = vv4;
        }
        __syncthreads();

        // mma1: S^T = K . Q^T
        float sacc[2][2][4];
        #pragma unroll
        for (int i = 0; i < 2; ++i)
            #pragma unroll
            for (int j = 0; j < 2; ++j)
                #pragma unroll
                for (int c = 0; c < 4; ++c) sacc[i][j][c] = 0.f;

        #pragma unroll
        for (int kk = 0; kk < 8; ++kk) {
            const int c0 = kk * 8 + t4;
            uint32_t ah[2][4], al[2][4];
            #pragma unroll
            for (int mt = 0; mt < 2; ++mt) {
                const int r0 = wm * 32 + mt * 16 + g;
                const int x = (r0 & 7) << 2;
                tfsplit(Ks[r0 * 64 + (c0 ^ x)],             ah[mt][0], al[mt][0]);
                tfsplit(Ks[(r0 + 8) * 64 + (c0 ^ x)],       ah[mt][1], al[mt][1]);
                tfsplit(Ks[r0 * 64 + ((c0 + 4) ^ x)],       ah[mt][2], al[mt][2]);
                tfsplit(Ks[(r0 + 8) * 64 + ((c0 + 4) ^ x)], ah[mt][3], al[mt][3]);
            }
            uint32_t bh_[2][2], bl_[2][2];
            #pragma unroll
            for (int nt = 0; nt < 2; ++nt) {
                const int nb = wn * 16 + nt * 8 + g;
                tfsplit(Qt[c0 * 64 + (nb ^ BXOR(c0))],           bh_[nt][0], bl_[nt][0]);
                tfsplit(Qt[(c0 + 4) * 64 + (nb ^ BXOR(c0 + 4))], bh_[nt][1], bl_[nt][1]);
            }
            #pragma unroll
            for (int mt = 0; mt < 2; ++mt)
                #pragma unroll
                for (int nt = 0; nt < 2; ++nt)
                    mma8_3x(sacc[mt][nt], ah[mt], al[mt], bh_[nt], bl_[nt]);
        }
        #pragma unroll
        for (int mt = 0; mt < 2; ++mt) {
            const int kvr = wm * 32 + mt * 16 + g;
            #pragma unroll
            for (int nt = 0; nt < 2; ++nt) {
                const int qc = wn * 16 + nt * 8 + 2 * t4;
                *(float2*)(&St[kvr * 64 + (qc ^ ((kvr & 3) << 3))]) =
                    make_float2(sacc[mt][nt][0], sacc[mt][nt][1]);
                *(float2*)(&St[(kvr + 8) * 64 + (qc ^ (((kvr + 8) & 3) << 3))]) =
                    make_float2(sacc[mt][nt][2], sacc[mt][nt][3]);
            }
        }
        __syncthreads();

        // online softmax over kv (columns of S^T)
        {
            const int q = tid & 63, kvg = tid >> 6;
            float sv[16];
            float mloc = -1e30f;
            #pragma unroll
            for (int r = 0; r < 16; ++r) {
                const int kv = kvg * 16 + r;
                sv[r] = St[kv * 64 + (q ^ ((kv & 3) << 3))];
                mloc = fmaxf(mloc, sv[r]);
            }
            pmax[kvg * 64 + q] = mloc;
            __syncthreads();
            const float mold = mrow[q];
            const float mnew = fmaxf(mold,
                fmaxf(fmaxf(pmax[q], pmax[64 + q]), fmaxf(pmax[128 + q], pmax[192 + q])));
            float sloc = 0.f;
            #pragma unroll
            for (int r = 0; r < 16; ++r) {
                const int kv = kvg * 16 + r;
                const float p = __expf(sv[r] - mnew);
                sloc += p;
                St[kv * 64 + (q ^ ((kv & 3) << 3))] = p;
            }
            psum[kvg * 64 + q] = sloc;
            __syncthreads();
            if (kvg == 0) {
                const float alpha = __expf(mold - mnew);
                lrow[q] = lrow[q] * alpha + psum[q] + psum[64 + q] + psum[128 + q] + psum[192 + q];
                mrow[q] = mnew;
                arow[q] = alpha;
            }
            __syncthreads();
        }

        // rescale O accumulators
        #pragma unroll
        for (int mt = 0; mt < 2; ++mt) {
            const int qr = wm * 32 + mt * 16 + g;
            const float al0 = arow[qr], al1 = arow[qr + 8];
            #pragma unroll
            for (int nt = 0; nt < 2; ++nt) {
                oacc[mt][nt][0] *= al0; oacc[mt][nt][1] *= al0;
                oacc[mt][nt][2] *= al1; oacc[mt][nt][3] *= al1;
            }
        }

        // mma2: O += P . V
        #pragma unroll
        for (int kk = 0; kk < 8; ++kk) {
            const int kvc = kk * 8 + t4;
            const int x0 = (kvc & 3) << 3;   // same for kvc and kvc+4
            uint32_t ah[2][4], al[2][4];
            #pragma unroll
            for (int mt = 0; mt < 2; ++mt) {
                const int qr = wm * 32 + mt * 16 + g;
                tfsplit(St[kvc * 64 + (qr ^ x0)],             ah[mt][0], al[mt][0]);
                tfsplit(St[kvc * 64 + ((qr + 8) ^ x0)],       ah[mt][1], al[mt][1]);
                tfsplit(St[(kvc + 4) * 64 + (qr ^ x0)],       ah[mt][2], al[mt][2]);
                tfsplit(St[(kvc + 4) * 64 + ((qr + 8) ^ x0)], ah[mt][3], al[mt][3]);
            }
            uint32_t bh_[2][2], bl_[2][2];
            #pragma unroll
            for (int nt = 0; nt < 2; ++nt) {
                const int db = wn * 16 + nt * 8 + g;
                tfsplit(Vs[kvc * 64 + (db ^ BXOR(kvc))],           bh_[nt][0], bl_[nt][0]);
                tfsplit(Vs[(kvc + 4) * 64 + (db ^ BXOR(kvc + 4))], bh_[nt][1], bl_[nt][1]);
            }
            #pragma unroll
            for (int mt = 0; mt < 2; ++mt)
                #pragma unroll
                for (int nt = 0; nt < 2; ++nt)
                    mma8_3x(oacc[mt][nt], ah[mt], al[mt], bh_[nt], bl_[nt]);
        }
    }

    // epilogue: /l, /sqrt(E)=32, merge heads
    #pragma unroll
    for (int mt = 0; mt < 2; ++mt) {
        const int qr = wm * 32 + mt * 16 + g;
        const float inv0 = 1.f / (lrow[qr] * 32.f);
        const float inv1 = 1.f / (lrow[qr + 8] * 32.f);
        #pragma unroll
        for (int nt = 0; nt < 2; ++nt) {
            const int dc = wn * 16 + nt * 8 + 2 * t4;
            *(float2*)(&out[((size_t)b * NN + q0 + qr) * EE + h * DD + dc]) =
                make_float2(oacc[mt][nt][0] * inv0, oacc[mt][nt][1] * inv0);
            *(float2*)(&out[((size_t)b * NN + q0 + qr + 8) * EE + h * DD + dc]) =
                make_float2(oacc[mt][nt][2] * inv1, oacc[mt][nt][3] * inv1);
        }
    }
}

// ---------------------------------------------------------------------------
// Launcher
// ---------------------------------------------------------------------------
extern "C" void kernel_launch(void* const* d_in, const int* in_sizes, int n_in,
                              void* d_out, int out_size)
{
    const float* queries = (const float*)d_in[0];
    const float* keys    = (const float*)d_in[1];
    const float* values  = (const float*)d_in[2];
    const float* Wq = (const float*)d_in[3];
    const float* bq = (const float*)d_in[4];
    const float* Wk = (const float*)d_in[5];
    const float* bk = (const float*)d_in[6];
    const float* Wv = (const float*)d_in[7];
    const float* bv = (const float*)d_in[8];
    const float* Wp = (const float*)d_in[9];
    const float* bp = (const float*)d_in[10];
    float* out = (float*)d_out;

    float *pq, *pk, *pv, *pao;
    cudaGetSymbolAddress((void**)&pq,  g_q);
    cudaGetSymbolAddress((void**)&pk,  g_k);
    cudaGetSymbolAddress((void**)&pv,  g_v);
    cudaGetSymbolAddress((void**)&pao, g_ao);

    const dim3 gemm_grid(EE / 128, MTOT / 128);   // (8, 32)
    gemm_tf32<1><<<gemm_grid, 256>>>(queries, Wq, bq, pq);
    gemm_tf32<1><<<gemm_grid, 256>>>(keys,    Wk, bk, pk);
    gemm_tf32<1><<<gemm_grid, 256>>>(values,  Wv, bv, pv);

    const int fa_smem = (4 * 64 * 64) * 4 + (3 * 64 + 2 * 256) * 4; // 68352
    cudaFuncSetAttribute(flash_tf32,
                         cudaFuncAttributeMaxDynamicSharedMemorySize, fa_smem);
    const dim3 fa_grid(NN / 64, BB * HH);         // (32, 32)
    flash_tf32<<<fa_grid, 256, fa_smem>>>(pq, pk, pv, pao);

    gemm_tf32<0><<<gemm_grid, 256>>>(pao, Wp, bp, out);
}

// round 5
// speedup vs baseline: 1.9157x; 1.3486x over previous
#include <cuda_runtime.h>
#include <stdint.h>

#define BB 2
#define NN 2048
#define EE 1024
#define HH 16
#define DD 64
#define MTOT (BB * NN)

// swizzle for B-operand tiles (row width 64/128 floats): xors bits 2-4 of n with k
#define BXOR(k) (((((k) & 3) << 3)) | ((((k) & 4) << 2)))

// ---------------------------------------------------------------------------
// Scratch
// ---------------------------------------------------------------------------
__device__ float g_q [BB * HH * NN * DD];
__device__ float g_k [BB * HH * NN * DD];
__device__ float g_v [BB * HH * NN * DD];
__device__ float g_ao[(size_t)MTOT * EE];

// ---------------------------------------------------------------------------
// Helpers
// ---------------------------------------------------------------------------
__device__ __forceinline__ uint32_t f2tf(float x) {
    uint32_t u;
    asm("cvt.rna.tf32.f32 %0, %1;" : "=r"(u) : "f"(x));
    return u;
}

// 3xTF32 split: x ~= hi + lo, both representable in tf32
__device__ __forceinline__ void tfsplit(float x, uint32_t& hi, uint32_t& lo) {
    hi = f2tf(x);
    lo = f2tf(x - __uint_as_float(hi));
}

__device__ __forceinline__ void mma8(float& c0, float& c1, float& c2, float& c3,
                                     uint32_t a0, uint32_t a1, uint32_t a2, uint32_t a3,
                                     uint32_t b0, uint32_t b1) {
    asm volatile(
        "mma.sync.aligned.m16n8k8.row.col.f32.tf32.tf32.f32 "
        "{%0,%1,%2,%3}, {%4,%5,%6,%7}, {%8,%9}, {%0,%1,%2,%3};\n"
        : "+f"(c0), "+f"(c1), "+f"(c2), "+f"(c3)
        : "r"(a0), "r"(a1), "r"(a2), "r"(a3), "r"(b0), "r"(b1));
}

// C += A*B with 3xtf32 compensation: Alo*Bhi + Ahi*Blo + Ahi*Bhi
__device__ __forceinline__ void mma8_3x(float* c,
                                        const uint32_t* ah, const uint32_t* al,
                                        const uint32_t* bh, const uint32_t* bl) {
    mma8(c[0], c[1], c[2], c[3], al[0], al[1], al[2], al[3], bh[0], bh[1]);
    mma8(c[0], c[1], c[2], c[3], ah[0], ah[1], ah[2], ah[3], bl[0], bl[1]);
    mma8(c[0], c[1], c[2], c[3], ah[0], ah[1], ah[2], ah[3], bh[0], bh[1]);
}

// ---------------------------------------------------------------------------
// 3xtf32 GEMM: Y[m,e] = X[m,:] . W[e,:] + bias[e]
// BM=128 BN=128 BK=32, 8 warps (2x4), warp tile 64x32, mma m16n8k8.
// hi/lo PRE-SPLIT into smem at tile load; inner loop is pure LDS + MMA.
// ---------------------------------------------------------------------------
template<int SCATTER>
__global__ __launch_bounds__(256, 2)
void gemm_tf32(const float* __restrict__ X,
               const float* __restrict__ W,
               const float* __restrict__ bias,
               float* __restrict__ Y)
{
    extern __shared__ uint32_t gsm[];
    uint32_t* Ah = gsm;                 // [m][k^((m&7)<<2)]  128*32
    uint32_t* Al = Ah + 128 * 32;
    uint32_t* Bh = Al + 128 * 32;       // [k][n^BXOR(k)]     32*128
    uint32_t* Bl = Bh + 32 * 128;

    const int tid  = threadIdx.x;
    const int lane = tid & 31;
    const int warp = tid >> 5;
    const int wm = warp >> 2, wn = warp & 3;
    const int g = lane >> 2, t4 = lane & 3;
    const int m0 = blockIdx.y * 128, n0 = blockIdx.x * 128;

    const int aRow = tid >> 3, aK4 = tid & 7;   // A loader
    const int bN = tid >> 1, bKh = tid & 1;     // B loader

    float acc[4][4][4];
    #pragma unroll
    for (int i = 0; i < 4; ++i)
        #pragma unroll
        for (int j = 0; j < 4; ++j)
            #pragma unroll
            for (int c = 0; c < 4; ++c) acc[i][j][c] = 0.f;

    const float* Xb = X + (size_t)m0 * EE;
    const float* Wb = W + (size_t)n0 * EE;

    for (int kt = 0; kt < EE; kt += 32) {
        __syncthreads();
        #pragma unroll
        for (int i = 0; i < 4; ++i) {
            const int m = aRow + 32 * i;
            float4 v = *(const float4*)(Xb + (size_t)m * EE + kt + aK4 * 4);
            uint4 uh, ul;
            tfsplit(v.x, uh.x, ul.x);
            tfsplit(v.y, uh.y, ul.y);
            tfsplit(v.z, uh.z, ul.z);
            tfsplit(v.w, uh.w, ul.w);
            const int idx = m * 32 + ((aK4 * 4) ^ ((m & 7) << 2));
            *(uint4*)(&Ah[idx]) = uh;
            *(uint4*)(&Al[idx]) = ul;
        }
        #pragma unroll
        for (int j = 0; j < 4; ++j) {
            const int kb = (2 * j + bKh) * 4;
            float4 v = *(const float4*)(Wb + (size_t)bN * EE + kt + kb);
            uint32_t h0, l0;
            tfsplit(v.x, h0, l0);
            Bh[(kb + 0) * 128 + (bN ^ BXOR(kb + 0))] = h0;
            Bl[(kb + 0) * 128 + (bN ^ BXOR(kb + 0))] = l0;
            tfsplit(v.y, h0, l0);
            Bh[(kb + 1) * 128 + (bN ^ BXOR(kb + 1))] = h0;
            Bl[(kb + 1) * 128 + (bN ^ BXOR(kb + 1))] = l0;
            tfsplit(v.z, h0, l0);
            Bh[(kb + 2) * 128 + (bN ^ BXOR(kb + 2))] = h0;
            Bl[(kb + 2) * 128 + (bN ^ BXOR(kb + 2))] = l0;
            tfsplit(v.w, h0, l0);
            Bh[(kb + 3) * 128 + (bN ^ BXOR(kb + 3))] = h0;
            Bl[(kb + 3) * 128 + (bN ^ BXOR(kb + 3))] = l0;
        }
        __syncthreads();

        #pragma unroll
        for (int kk = 0; kk < 4; ++kk) {
            const int c0 = kk * 8 + t4;
            uint32_t bhf[4][2], blf[4][2];
            #pragma unroll
            for (int nt = 0; nt < 4; ++nt) {
                const int nb = wn * 32 + nt * 8 + g;
                const int i0 = c0 * 128 + (nb ^ BXOR(c0));
                const int i1 = (c0 + 4) * 128 + (nb ^ BXOR(c0 + 4));
                bhf[nt][0] = Bh[i0]; blf[nt][0] = Bl[i0];
                bhf[nt][1] = Bh[i1]; blf[nt][1] = Bl[i1];
            }
            #pragma unroll
            for (int mt = 0; mt < 4; ++mt) {
                const int r0 = wm * 64 + mt * 16 + g;
                const int x = (r0 & 7) << 2;
                const int i0 = r0 * 32 + (c0 ^ x);
                const int i1 = (r0 + 8) * 32 + (c0 ^ x);
                const int i2 = r0 * 32 + ((c0 + 4) ^ x);
                const int i3 = (r0 + 8) * 32 + ((c0 + 4) ^ x);
                uint32_t ah[4] = {Ah[i0], Ah[i1], Ah[i2], Ah[i3]};
                uint32_t al[4] = {Al[i0], Al[i1], Al[i2], Al[i3]};
                #pragma unroll
                for (int nt = 0; nt < 4; ++nt)
                    mma8_3x(acc[mt][nt], ah, al, bhf[nt], blf[nt]);
            }
        }
    }

    #pragma unroll
    for (int mt = 0; mt < 4; ++mt) {
        const int r0 = m0 + wm * 64 + mt * 16 + g;
        #pragma unroll
        for (int nt = 0; nt < 4; ++nt) {
            const int c = n0 + wn * 32 + nt * 8 + 2 * t4;
            const float bv0 = bias[c], bv1 = bias[c + 1];
            float2 v0 = make_float2(acc[mt][nt][0] + bv0, acc[mt][nt][1] + bv1);
            float2 v1 = make_float2(acc[mt][nt][2] + bv0, acc[mt][nt][3] + bv1);
            if (SCATTER) {
                const int h = c >> 6, d = c & 63;
                const int b0i = r0 >> 11, n0i = r0 & (NN - 1);
                *(float2*)(&Y[((((size_t)b0i * HH + h) * NN) + n0i) * DD + d]) = v0;
                const int r1 = r0 + 8;
                const int b1i = r1 >> 11, n1i = r1 & (NN - 1);
                *(float2*)(&Y[((((size_t)b1i * HH + h) * NN) + n1i) * DD + d]) = v1;
            } else {
                *(float2*)(&Y[(size_t)r0 * EE + c]) = v0;
                *(float2*)(&Y[(size_t)(r0 + 8) * EE + c]) = v1;
            }
        }
    }
}

// ---------------------------------------------------------------------------
// Flash attention. BQ=64, BKV=64, 8 warps (2x4).
// mma1 (3xtf32): S^T[kv][q] = K . Q^T    K,Q pre-split hi/lo in smem
// softmax column-wise over kv (online m/l), quirk: /sqrt(E)=32 post-softmax
// mma2 (1xtf32): O[q][d] += P . V        P,V stored tf32-rounded (error ~1e-4)
// ---------------------------------------------------------------------------
__global__ __launch_bounds__(256)
void flash_tf32(const float* __restrict__ qb,
                const float* __restrict__ kb,
                const float* __restrict__ vb,
                float* __restrict__ out)
{
    extern __shared__ char smraw[];
    uint32_t* Qh = (uint32_t*)smraw;       // [d][q ^ BXOR(d)]
    uint32_t* Ql = Qh + 64 * 64;
    uint32_t* Kh = Ql + 64 * 64;           // [kv][d ^ ((kv&7)<<2)]
    uint32_t* Kl = Kh + 64 * 64;
    uint32_t* Vs = Kl + 64 * 64;           // [kv][d ^ BXOR(kv)]  tf32-rounded
    float*    St = (float*)(Vs + 64 * 64); // [kv][q ^ ((kv&3)<<3)]
    float* mrow = St + 64 * 64;
    float* lrow = mrow + 64;
    float* arow = lrow + 64;
    float* pmax = arow + 64;               // [4][64]
    float* psum = pmax + 256;              // [4][64]

    const int tid  = threadIdx.x;
    const int lane = tid & 31;
    const int warp = tid >> 5;
    const int wm = warp >> 2, wn = warp & 3;
    const int g = lane >> 2, t4 = lane & 3;

    const int q0 = blockIdx.x * 64;
    const int bh = blockIdx.y;
    const int b  = bh >> 4;
    const int h  = bh & (HH - 1);

    if (tid < 64) { mrow[tid] = -1e30f; lrow[tid] = 0.f; }

    // Q transpose + hi/lo split (once per block, reused 32 tiles)
    const float* Qg = qb + ((size_t)bh * NN + q0) * DD;
    const int d4 = tid & 15, row0 = tid >> 4;
    #pragma unroll
    for (int i = 0; i < 4; ++i) {
        const int q = row0 + 16 * i;
        float4 v = *(const float4*)(Qg + (size_t)q * DD + d4 * 4);
        const int dd = d4 * 4;
        uint32_t hh, ll;
        tfsplit(v.x, hh, ll);
        Qh[(dd + 0) * 64 + (q ^ BXOR(dd + 0))] = hh;
        Ql[(dd + 0) * 64 + (q ^ BXOR(dd + 0))] = ll;
        tfsplit(v.y, hh, ll);
        Qh[(dd + 1) * 64 + (q ^ BXOR(dd + 1))] = hh;
        Ql[(dd + 1) * 64 + (q ^ BXOR(dd + 1))] = ll;
        tfsplit(v.z, hh, ll);
        Qh[(dd + 2) * 64 + (q ^ BXOR(dd + 2))] = hh;
        Ql[(dd + 2) * 64 + (q ^ BXOR(dd + 2))] = ll;
        tfsplit(v.w, hh, ll);
        Qh[(dd + 3) * 64 + (q ^ BXOR(dd + 3))] = hh;
        Ql[(dd + 3) * 64 + (q ^ BXOR(dd + 3))] = ll;
    }

    float oacc[2][2][4];
    #pragma unroll
    for (int i = 0; i < 2; ++i)
        #pragma unroll
        for (int j = 0; j < 2; ++j)
            #pragma unroll
            for (int c = 0; c < 4; ++c) oacc[i][j][c] = 0.f;

    const float* Kg = kb + (size_t)bh * NN * DD;
    const float* Vg = vb + (size_t)bh * NN * DD;

    for (int kv0 = 0; kv0 < NN; kv0 += 64) {
        __syncthreads();
        #pragma unroll
        for (int i = 0; i < 4; ++i) {
            const int kv = row0 + 16 * i;
            float4 kv4 = *(const float4*)(Kg + (size_t)(kv0 + kv) * DD + d4 * 4);
            float4 vv4 = *(const float4*)(Vg + (size_t)(kv0 + kv) * DD + d4 * 4);
            uint4 kh, kl;
            tfsplit(kv4.x, kh.x, kl.x);
            tfsplit(kv4.y, kh.y, kl.y);
            tfsplit(kv4.z, kh.z, kl.z);
            tfsplit(kv4.w, kh.w, kl.w);
            const int kidx = kv * 64 + ((d4 * 4) ^ ((kv & 7) << 2));
            *(uint4*)(&Kh[kidx]) = kh;
            *(uint4*)(&Kl[kidx]) = kl;
            uint4 vu = make_uint4(f2tf(vv4.x), f2tf(vv4.y), f2tf(vv4.z), f2tf(vv4.w));
            *(uint4*)(&Vs[kv * 64 + ((d4 * 4) ^ BXOR(kv))]) = vu;
        }
        __syncthreads();

        // mma1: S^T = K . Q^T  (3xtf32)
        float sacc[2][2][4];
        #pragma unroll
        for (int i = 0; i < 2; ++i)
            #pragma unroll
            for (int j = 0; j < 2; ++j)
                #pragma unroll
                for (int c = 0; c < 4; ++c) sacc[i][j][c] = 0.f;

        #pragma unroll
        for (int kk = 0; kk < 8; ++kk) {
            const int c0 = kk * 8 + t4;
            uint32_t ah[2][4], al[2][4];
            #pragma unroll
            for (int mt = 0; mt < 2; ++mt) {
                const int r0 = wm * 32 + mt * 16 + g;
                const int x = (r0 & 7) << 2;
                const int i0 = r0 * 64 + (c0 ^ x);
                const int i1 = (r0 + 8) * 64 + (c0 ^ x);
                const int i2 = r0 * 64 + ((c0 + 4) ^ x);
                const int i3 = (r0 + 8) * 64 + ((c0 + 4) ^ x);
                ah[mt][0] = Kh[i0]; al[mt][0] = Kl[i0];
                ah[mt][1] = Kh[i1]; al[mt][1] = Kl[i1];
                ah[mt][2] = Kh[i2]; al[mt][2] = Kl[i2];
                ah[mt][3] = Kh[i3]; al[mt][3] = Kl[i3];
            }
            uint32_t bh_[2][2], bl_[2][2];
            #pragma unroll
            for (int nt = 0; nt < 2; ++nt) {
                const int nb = wn * 16 + nt * 8 + g;
                const int i0 = c0 * 64 + (nb ^ BXOR(c0));
                const int i1 = (c0 + 4) * 64 + (nb ^ BXOR(c0 + 4));
                bh_[nt][0] = Qh[i0]; bl_[nt][0] = Ql[i0];
                bh_[nt][1] = Qh[i1]; bl_[nt][1] = Ql[i1];
            }
            #pragma unroll
            for (int mt = 0; mt < 2; ++mt)
                #pragma unroll
                for (int nt = 0; nt < 2; ++nt)
                    mma8_3x(sacc[mt][nt], ah[mt], al[mt], bh_[nt], bl_[nt]);
        }
        #pragma unroll
        for (int mt = 0; mt < 2; ++mt) {
            const int kvr = wm * 32 + mt * 16 + g;
            #pragma unroll
            for (int nt = 0; nt < 2; ++nt) {
                const int qc = wn * 16 + nt * 8 + 2 * t4;
                *(float2*)(&St[kvr * 64 + (qc ^ ((kvr & 3) << 3))]) =
                    make_float2(sacc[mt][nt][0], sacc[mt][nt][1]);
                *(float2*)(&St[(kvr + 8) * 64 + (qc ^ (((kvr + 8) & 3) << 3))]) =
                    make_float2(sacc[mt][nt][2], sacc[mt][nt][3]);
            }
        }
        __syncthreads();

        // online softmax over kv (columns of S^T); write back tf32-rounded p
        {
            const int q = tid & 63, kvg = tid >> 6;
            float sv[16];
            float mloc = -1e30f;
            #pragma unroll
            for (int r = 0; r < 16; ++r) {
                const int kv = kvg * 16 + r;
                sv[r] = St[kv * 64 + (q ^ ((kv & 3) << 3))];
                mloc = fmaxf(mloc, sv[r]);
            }
            pmax[kvg * 64 + q] = mloc;
            __syncthreads();
            const float mold = mrow[q];
            const float mnew = fmaxf(mold,
                fmaxf(fmaxf(pmax[q], pmax[64 + q]), fmaxf(pmax[128 + q], pmax[192 + q])));
            float sloc = 0.f;
            #pragma unroll
            for (int r = 0; r < 16; ++r) {
                const int kv = kvg * 16 + r;
                const float p = __expf(sv[r] - mnew);
                sloc += p;
                St[kv * 64 + (q ^ ((kv & 3) << 3))] = __uint_as_float(f2tf(p));
            }
            psum[kvg * 64 + q] = sloc;
            __syncthreads();
            if (kvg == 0) {
                const float alpha = __expf(mold - mnew);
                lrow[q] = lrow[q] * alpha + psum[q] + psum[64 + q] + psum[128 + q] + psum[192 + q];
                mrow[q] = mnew;
                arow[q] = alpha;
            }
            __syncthreads();
        }

        // rescale O accumulators
        #pragma unroll
        for (int mt = 0; mt < 2; ++mt) {
            const int qr = wm * 32 + mt * 16 + g;
            const float al0 = arow[qr], al1 = arow[qr + 8];
            #pragma unroll
            for (int nt = 0; nt < 2; ++nt) {
                oacc[mt][nt][0] *= al0; oacc[mt][nt][1] *= al0;
                oacc[mt][nt][2] *= al1; oacc[mt][nt][3] *= al1;
            }
        }

        // mma2: O += P . V  (single tf32 mma; P, V tf32-rounded)
        #pragma unroll
        for (int kk = 0; kk < 8; ++kk) {
            const int kvc = kk * 8 + t4;
            const int x0 = (kvc & 3) << 3;   // same for kvc and kvc+4
            uint32_t af[2][4];
            #pragma unroll
            for (int mt = 0; mt < 2; ++mt) {
                const int qr = wm * 32 + mt * 16 + g;
                af[mt][0] = __float_as_uint(St[kvc * 64 + (qr ^ x0)]);
                af[mt][1] = __float_as_uint(St[kvc * 64 + ((qr + 8) ^ x0)]);
                af[mt][2] = __float_as_uint(St[(kvc + 4) * 64 + (qr ^ x0)]);
                af[mt][3] = __float_as_uint(St[(kvc + 4) * 64 + ((qr + 8) ^ x0)]);
            }
            uint32_t bf[2][2];
            #pragma unroll
            for (int nt = 0; nt < 2; ++nt) {
                const int db = wn * 16 + nt * 8 + g;
                bf[nt][0] = Vs[kvc * 64 + (db ^ BXOR(kvc))];
                bf[nt][1] = Vs[(kvc + 4) * 64 + (db ^ BXOR(kvc + 4))];
            }
            #pragma unroll
            for (int mt = 0; mt < 2; ++mt)
                #pragma unroll
                for (int nt = 0; nt < 2; ++nt)
                    mma8(oacc[mt][nt][0], oacc[mt][nt][1], oacc[mt][nt][2], oacc[mt][nt][3],
                         af[mt][0], af[mt][1], af[mt][2], af[mt][3],
                         bf[nt][0], bf[nt][1]);
        }
    }

    // epilogue: /l, /sqrt(E)=32, merge heads
    #pragma unroll
    for (int mt = 0; mt < 2; ++mt) {
        const int qr = wm * 32 + mt * 16 + g;
        const float inv0 = 1.f / (lrow[qr] * 32.f);
        const float inv1 = 1.f / (lrow[qr + 8] * 32.f);
        #pragma unroll
        for (int nt = 0; nt < 2; ++nt) {
            const int dc = wn * 16 + nt * 8 + 2 * t4;
            *(float2*)(&out[((size_t)b * NN + q0 + qr) * EE + h * DD + dc]) =
                make_float2(oacc[mt][nt][0] * inv0, oacc[mt][nt][1] * inv0);
            *(float2*)(&out[((size_t)b * NN + q0 + qr + 8) * EE + h * DD + dc]) =
                make_float2(oacc[mt][nt][2] * inv1, oacc[mt][nt][3] * inv1);
        }
    }
}

// ---------------------------------------------------------------------------
// Launcher
// ---------------------------------------------------------------------------
extern "C" void kernel_launch(void* const* d_in, const int* in_sizes, int n_in,
                              void* d_out, int out_size)
{
    const float* queries = (const float*)d_in[0];
    const float* keys    = (const float*)d_in[1];
    const float* values  = (const float*)d_in[2];
    const float* Wq = (const float*)d_in[3];
    const float* bq = (const float*)d_in[4];
    const float* Wk = (const float*)d_in[5];
    const float* bk = (const float*)d_in[6];
    const float* Wv = (const float*)d_in[7];
    const float* bv = (const float*)d_in[8];
    const float* Wp = (const float*)d_in[9];
    const float* bp = (const float*)d_in[10];
    float* out = (float*)d_out;

    float *pq, *pk, *pv, *pao;
    cudaGetSymbolAddress((void**)&pq,  g_q);
    cudaGetSymbolAddress((void**)&pk,  g_k);
    cudaGetSymbolAddress((void**)&pv,  g_v);
    cudaGetSymbolAddress((void**)&pao, g_ao);

    const int gemm_smem = 4 * 128 * 32 * (int)sizeof(uint32_t); // 65536
    cudaFuncSetAttribute(gemm_tf32<1>,
                         cudaFuncAttributeMaxDynamicSharedMemorySize, gemm_smem);
    cudaFuncSetAttribute(gemm_tf32<0>,
                         cudaFuncAttributeMaxDynamicSharedMemorySize, gemm_smem);

    const dim3 gemm_grid(EE / 128, MTOT / 128);   // (8, 32)
    gemm_tf32<1><<<gemm_grid, 256, gemm_smem>>>(queries, Wq, bq, pq);
    gemm_tf32<1><<<gemm_grid, 256, gemm_smem>>>(keys,    Wk, bk, pk);
    gemm_tf32<1><<<gemm_grid, 256, gemm_smem>>>(values,  Wv, bv, pv);

    const int fa_smem = (6 * 64 * 64) * 4 + (3 * 64 + 2 * 256) * 4; // 101120
    cudaFuncSetAttribute(flash_tf32,
                         cudaFuncAttributeMaxDynamicSharedMemorySize, fa_smem);
    const dim3 fa_grid(NN / 64, BB * HH);         // (32, 32)
    flash_tf32<<<fa_grid, 256, fa_smem>>>(pq, pk, pv, pao);

    gemm_tf32<0><<<gemm_grid, 256, gemm_smem>>>(pao, Wp, bp, out);
}